// round 12
// baseline (speedup 1.0000x reference)
#include <cuda_runtime.h>
#include <cuda_fp16.h>
#include <mma.h>
#include <cstddef>
#include <cstdint>

using namespace nvcuda;

// Problem constants
#define BATCH 128
#define HH 14
#define WW 14
#define CC 768
#define NHEAD 12
#define HDIM 64
#define HWSZ 196          // 14*14
#define C3 2304           // 3*C
#define MROWS 25088       // BATCH*HWSZ
#define NHEADS_TOTAL 1536 // BATCH*NHEAD

#define LOG2E 1.442695040888963f

// Scratch buffers (device globals: no allocation allowed)
__device__ float  g_qkv[(size_t)MROWS * C3];  // qkv GEMM out (fp32)
__device__ __half g_att[(size_t)MROWS * CC];  // attention out (fp16)
__device__ __half g_x[(size_t)MROWS * CC];    // x (fp16)
__device__ __half g_wqkv[(size_t)CC * C3];    // w_qkv (fp16)
__device__ __half g_wproj[(size_t)CC * CC];   // w_proj (fp16)

// ---------------------------------------------------------------------------
// helpers
// ---------------------------------------------------------------------------
__global__ void to_half_kernel(const float* __restrict__ in,
                               __half* __restrict__ out, int n4)
{
    int i = blockIdx.x * blockDim.x + threadIdx.x;
    if (i < n4) {
        float4 v = ((const float4*)in)[i];
        __half2 a = __floats2half2_rn(v.x, v.y);
        __half2 b = __floats2half2_rn(v.z, v.w);
        uint2 pk;
        pk.x = *(uint32_t*)&a;
        pk.y = *(uint32_t*)&b;
        ((uint2*)out)[i] = pk;
    }
}

// Packed 2^x for two fp32 args via f16x2 MUFU (1 EX2 for 2 values).
__device__ __forceinline__ float2 exp2_2(float a, float b) {
    uint32_t h, e;
    asm("cvt.rn.f16x2.f32 %0, %1, %2;" : "=r"(h) : "f"(b), "f"(a)); // hi=b, lo=a
    asm("ex2.approx.f16x2 %0, %1;" : "=r"(e) : "r"(h));
    float2 r;
    asm("{.reg .f16 lo, hi;\n\t"
        "mov.b32 {lo, hi}, %2;\n\t"
        "cvt.f32.f16 %0, lo;\n\t"
        "cvt.f32.f16 %1, hi;}"
        : "=f"(r.x), "=f"(r.y) : "r"(e));
    return r;
}

__device__ __forceinline__ void cpa16(void* s, const void* g) {
    uint32_t sa = (uint32_t)__cvta_generic_to_shared(s);
    asm volatile("cp.async.cg.shared.global [%0], [%1], 16;\n" ::"r"(sa), "l"(g));
}
__device__ __forceinline__ void cpa_commit() {
    asm volatile("cp.async.commit_group;\n" ::);
}
template <int N>
__device__ __forceinline__ void cpa_wait() {
    asm volatile("cp.async.wait_group %0;\n" ::"n"(N));
}

// ---------------------------------------------------------------------------
// Pipelined fp16 GEMM: C(fp32) = A(MxK,f16) @ B(KxN,f16) + bias(fp32)
// BM=BN=128, BK=64, wmma m16n16k16, 2-stage cp.async, 256 thr, 2 CTA/SM.
// Direct fp32 store_matrix_sync epilogue (fast tail).
// ---------------------------------------------------------------------------
#define BM 128
#define BN 128
#define BK 64
#define BSTR 136   // halves per B row: 128 + 8 pad
#define ASTRH 72   // halves per A row: 64 + 8 pad

#define GEMM_SMEM_BYTES ((2 * BM * ASTRH + 2 * BK * BSTR) * 2 + 16 * BSTR * 4)

__device__ __forceinline__ void gemm_body(
    const __half* __restrict__ A, const __half* __restrict__ Bm,
    const float* __restrict__ bias, float* __restrict__ Cout,
    int M, int N, int K)
{
    extern __shared__ char smraw[];
    __half* As = (__half*)smraw;                       // 2 x BM x ASTRH
    __half* Bs = As + 2 * BM * ASTRH;                  // 2 x BK x BSTR
    float* biasT = (float*)(Bs + 2 * BK * BSTR);       // 16 x BSTR fp32

    const int tid = threadIdx.x;
    const int m0 = blockIdx.y * BM;
    const int n0 = blockIdx.x * BN;

    for (int i = tid; i < 16 * BN; i += 256) {
        int rr = i >> 7, cc = i & 127;
        biasT[rr * BSTR + cc] = bias[n0 + cc];
    }
    __syncthreads();

    const int w  = tid >> 5;
    const int wm = w >> 2;
    const int wn = w & 3;

    wmma::fragment<wmma::accumulator, 16, 16, 16, float> acc[4][2];
#pragma unroll
    for (int i = 0; i < 4; i++)
#pragma unroll
        for (int j = 0; j < 2; j++)
            wmma::load_matrix_sync(acc[i][j], &biasT[wn * 32 + j * 16], BSTR,
                                   wmma::mem_row_major);

    const int arow = tid >> 3, ac8 = (tid & 7) * 8;
    const int brow = tid >> 4, bc8 = (tid & 15) * 8;

    const int T = K / BK;

    {
        const __half* ag = &A[(size_t)(m0 + arow) * K + ac8];
        const __half* bg = &Bm[(size_t)brow * N + n0 + bc8];
#pragma unroll
        for (int p = 0; p < 4; p++)
            cpa16(&As[(arow + p * 32) * ASTRH + ac8], ag + (size_t)(p * 32) * K);
#pragma unroll
        for (int p = 0; p < 4; p++)
            cpa16(&Bs[(brow + p * 16) * BSTR + bc8], bg + (size_t)(p * 16) * N);
        cpa_commit();
    }

    for (int t = 0; t < T; t++) {
        if (t + 1 < T) {
            const int st = (t + 1) & 1;
            const int kt = (t + 1) * BK;
            const __half* ag = &A[(size_t)(m0 + arow) * K + kt + ac8];
            const __half* bg = &Bm[(size_t)(kt + brow) * N + n0 + bc8];
            __half* asd = &As[st * BM * ASTRH];
            __half* bsd = &Bs[st * BK * BSTR];
#pragma unroll
            for (int p = 0; p < 4; p++)
                cpa16(&asd[(arow + p * 32) * ASTRH + ac8], ag + (size_t)(p * 32) * K);
#pragma unroll
            for (int p = 0; p < 4; p++)
                cpa16(&bsd[(brow + p * 16) * BSTR + bc8], bg + (size_t)(p * 16) * N);
            cpa_commit();
            cpa_wait<1>();
        } else {
            cpa_wait<0>();
        }
        __syncthreads();

        const __half* asrc = &As[(t & 1) * BM * ASTRH];
        const __half* bsrc = &Bs[(t & 1) * BK * BSTR];

#pragma unroll
        for (int kk = 0; kk < BK; kk += 16) {
            wmma::fragment<wmma::matrix_a, 16, 16, 16, __half, wmma::row_major> af[4];
            wmma::fragment<wmma::matrix_b, 16, 16, 16, __half, wmma::row_major> bf[2];
#pragma unroll
            for (int i = 0; i < 4; i++)
                wmma::load_matrix_sync(af[i], &asrc[(wm * 64 + i * 16) * ASTRH + kk], ASTRH);
#pragma unroll
            for (int j = 0; j < 2; j++)
                wmma::load_matrix_sync(bf[j], &bsrc[kk * BSTR + wn * 32 + j * 16], BSTR);
#pragma unroll
            for (int i = 0; i < 4; i++)
#pragma unroll
                for (int j = 0; j < 2; j++)
                    wmma::mma_sync(acc[i][j], af[i], bf[j], acc[i][j]);
        }
        __syncthreads();
    }

#pragma unroll
    for (int i = 0; i < 4; i++)
#pragma unroll
        for (int j = 0; j < 2; j++)
            wmma::store_matrix_sync(
                Cout + (size_t)(m0 + wm * 64 + i * 16) * N + n0 + wn * 32 + j * 16,
                acc[i][j], N, wmma::mem_row_major);
}

__global__ __launch_bounds__(256, 2) void gemm_qkv_k(const float* __restrict__ bias)
{
    gemm_body(g_x, g_wqkv, bias, g_qkv, MROWS, C3, CC);
}

__global__ __launch_bounds__(256, 2) void gemm_proj_k(
    const float* __restrict__ bias, float* __restrict__ C)
{
    gemm_body(g_att, g_wproj, bias, C, MROWS, CC, CC);
}

// ---------------------------------------------------------------------------
// Tensorized fp16 attention: one CTA per (batch, head), 512 threads (16 warps).
// K (rows 0..195) + rel tables (rows 224..250 Rh, 256..282 Rw) in fp16 smem
// (converted from fp32 g_qkv during staging); V resident; queries in 4 blocks
// of 64 rows. QK^T wmma -> log2-softmax (packed f16 EX2, norm folded into
// fp16 P) -> PV wmma -> fp16 out.
// ---------------------------------------------------------------------------
#define AKSTR 72      // halves per K/V/Q row (64 + 8 pad)
#define SSTRF 296     // fp32 S row stride
#define PSTR 232      // halves per P row

#define ASM_K (288 * AKSTR)
#define ASM_V (224 * AKSTR)
#define ASM_Q (64 * AKSTR)
#define ASM_P (64 * PSTR)
#define ASM_S (64 * SSTRF)
#define ATTN_SMEM_BYTES ((ASM_K + ASM_V + ASM_Q + ASM_P) * 2 + ASM_S * 4)

__global__ __launch_bounds__(512) void attn_kernel(
    const float* __restrict__ rph, const float* __restrict__ rpw)
{
    extern __shared__ char smraw[];
    __half* kS = (__half*)smraw;
    __half* vS = kS + ASM_K;
    __half* qS = vS + ASM_V;
    __half* pS = qS + ASM_Q;
    float*  sS = (float*)(pS + ASM_P);

    const int tid = threadIdx.x;
    const int wid = tid >> 5, lane = tid & 31;
    const int head = blockIdx.x;
    const int b = head / NHEAD;
    const int h = head % NHEAD;

    const float* gbase = g_qkv + (size_t)b * HWSZ * C3 + h * HDIM;

    // Zero pad rows: kS 196..223, 251..255, 283..287; vS 196..223
    {
        const uint4 z = make_uint4(0, 0, 0, 0);
        for (int i = tid; i < 28 * 9; i += 512) ((uint4*)(kS + 196 * AKSTR))[i] = z;
        for (int i = tid; i < 5 * 9; i += 512) {
            ((uint4*)(kS + 251 * AKSTR))[i] = z;
            ((uint4*)(kS + 283 * AKSTR))[i] = z;
        }
        for (int i = tid; i < 28 * 9; i += 512) ((uint4*)(vS + 196 * AKSTR))[i] = z;
    }
    // Stage K, V from fp32 with inline fp16 conversion (coalesced float2 LDG)
    for (int i = tid; i < HWSZ * 32; i += 512) {
        int j = i >> 5, c2 = (i & 31) * 2;
        const float* p = gbase + (size_t)j * C3 + c2;
        float2 kv = *(const float2*)(p + 768);
        float2 vv = *(const float2*)(p + 1536);
        *(__half2*)(kS + j * AKSTR + c2) = __floats2half2_rn(kv.x, kv.y);
        *(__half2*)(vS + j * AKSTR + c2) = __floats2half2_rn(vv.x, vv.y);
    }
    // Rel tables (fp32 -> fp16) as extra key rows
    for (int i = tid; i < 27 * HDIM; i += 512) {
        int r = i >> 6, d = i & 63;
        kS[(224 + r) * AKSTR + d] = __float2half(rph[i]);
        kS[(256 + r) * AKSTR + d] = __float2half(rpw[i]);
    }
    __syncthreads();

    for (int blk = 0; blk < 4; blk++) {
        const int r0 = blk * 64;

        // --- Stage Q block (64 x 64 fp16 from fp32), zero invalid rows ---
        for (int i = tid; i < 64 * 32; i += 512) {
            int r = i >> 5, c2 = (i & 31) * 2;
            __half2 v = __floats2half2_rn(0.f, 0.f);
            if (r0 + r < HWSZ) {
                float2 q = *(const float2*)(gbase + (size_t)(r0 + r) * C3 + c2);
                v = __floats2half2_rn(q.x, q.y);
            }
            *(__half2*)(qS + r * AKSTR + c2) = v;
        }
        __syncthreads();

        // --- QK^T (+rel cols): 4x18 tiles of 16x16, k=64 ---
        for (int t = wid; t < 72; t += 16) {
            const int mt = t / 18, nt = t % 18;
            wmma::fragment<wmma::accumulator, 16, 16, 16, float> acc;
            wmma::fill_fragment(acc, 0.f);
#pragma unroll
            for (int ks = 0; ks < 4; ks++) {
                wmma::fragment<wmma::matrix_a, 16, 16, 16, __half, wmma::row_major> af;
                wmma::fragment<wmma::matrix_b, 16, 16, 16, __half, wmma::col_major> bf;
                wmma::load_matrix_sync(af, qS + mt * 16 * AKSTR + ks * 16, AKSTR);
                wmma::load_matrix_sync(bf, kS + nt * 16 * AKSTR + ks * 16, AKSTR);
                wmma::mma_sync(acc, af, bf, acc);
            }
            wmma::store_matrix_sync(sS + mt * 16 * SSTRF + nt * 16, acc, SSTRF,
                                    wmma::mem_row_major);
        }
        __syncthreads();

        // --- Softmax (8 threads/row, 28 cols each), P = e/sum in fp16 ---
        {
            const int r = tid >> 3, sub = tid & 7;
            const int qr = r0 + r;
            const int qv = (qr < HWSZ) ? qr : 0;
            const int hq = qv / 14, wq = qv % 14;
            const float* srow = sS + r * SSTRF;
            float e[28];
            float lsum = 0.f;
#pragma unroll
            for (int i = 0; i < 28; i += 2) {
                float s01[2];
#pragma unroll
                for (int u = 0; u < 2; u++) {
                    int j = sub + (i + u) * 8;
                    if (j < HWSZ) {
                        int i1 = hq - j / 14 + 13;
                        int i2 = wq - j % 14 + 13;
                        s01[u] = (srow[j] * 0.125f + srow[224 + i1] + srow[256 + i2])
                                 * LOG2E;
                    } else {
                        s01[u] = -30.0f;  // exp2 -> 0 in f16
                    }
                }
                float2 ee = exp2_2(s01[0], s01[1]);
                e[i] = ee.x;
                e[i + 1] = ee.y;
                lsum += ee.x + ee.y;
            }
#pragma unroll
            for (int o = 4; o > 0; o >>= 1)
                lsum += __shfl_xor_sync(0xffffffffu, lsum, o);
            const float inv = 1.f / lsum;
            __half* prow = pS + r * PSTR;
#pragma unroll
            for (int i = 0; i < 28; i++)
                prow[sub + i * 8] = __float2half(e[i] * inv);
        }
        __syncthreads();

        // --- PV: 4x4 tiles of 16x16, k=224 (14 steps); O -> sS ---
        {
            const int mt = wid >> 2, nt = wid & 3;
            wmma::fragment<wmma::accumulator, 16, 16, 16, float> acc;
            wmma::fill_fragment(acc, 0.f);
#pragma unroll
            for (int ks = 0; ks < 14; ks++) {
                wmma::fragment<wmma::matrix_a, 16, 16, 16, __half, wmma::row_major> af;
                wmma::fragment<wmma::matrix_b, 16, 16, 16, __half, wmma::row_major> bf;
                wmma::load_matrix_sync(af, pS + mt * 16 * PSTR + ks * 16, PSTR);
                wmma::load_matrix_sync(bf, vS + ks * 16 * AKSTR + nt * 16, AKSTR);
                wmma::mma_sync(acc, af, bf, acc);
            }
            wmma::store_matrix_sync(sS + mt * 16 * SSTRF + nt * 16, acc, SSTRF,
                                    wmma::mem_row_major);
        }
        __syncthreads();

        // --- Store valid O rows (fp16) ---
        {
            const int nv = (HWSZ - r0 < 64) ? (HWSZ - r0) : 64;
            __half* gout = g_att + ((size_t)b * HWSZ + r0) * CC + h * HDIM;
            for (int idx = tid; idx < 64 * 32; idx += 512) {
                int r = idx >> 5, c2 = idx & 31;
                if (r < nv) {
                    __half2 v = __floats2half2_rn(sS[r * SSTRF + c2 * 2],
                                                  sS[r * SSTRF + c2 * 2 + 1]);
                    *(__half2*)(gout + (size_t)r * CC + c2 * 2) = v;
                }
            }
        }
        __syncthreads();
    }
}

// ---------------------------------------------------------------------------
extern "C" void kernel_launch(void* const* d_in, const int* in_sizes, int n_in,
                              void* d_out, int out_size)
{
    const float* x      = (const float*)d_in[0]; // (25088, 768)
    const float* w_qkv  = (const float*)d_in[1]; // (768, 2304)
    const float* b_qkv  = (const float*)d_in[2]; // (2304,)
    const float* rph    = (const float*)d_in[3]; // (27, 64)
    const float* rpw    = (const float*)d_in[4]; // (27, 64)
    const float* w_proj = (const float*)d_in[5]; // (768, 768)
    const float* b_proj = (const float*)d_in[6]; // (768,)
    float* out = (float*)d_out;                  // (25088, 768)

    __half *d_x, *d_wqkv, *d_wproj;
    cudaGetSymbolAddress((void**)&d_x, g_x);
    cudaGetSymbolAddress((void**)&d_wqkv, g_wqkv);
    cudaGetSymbolAddress((void**)&d_wproj, g_wproj);

    cudaFuncSetAttribute(gemm_qkv_k,
                         cudaFuncAttributeMaxDynamicSharedMemorySize,
                         GEMM_SMEM_BYTES);
    cudaFuncSetAttribute(gemm_proj_k,
                         cudaFuncAttributeMaxDynamicSharedMemorySize,
                         GEMM_SMEM_BYTES);
    cudaFuncSetAttribute(attn_kernel,
                         cudaFuncAttributeMaxDynamicSharedMemorySize,
                         ATTN_SMEM_BYTES);

    // Convert GEMM inputs to fp16
    {
        int n4 = MROWS * CC / 4;
        to_half_kernel<<<(n4 + 255) / 256, 256>>>(x, d_x, n4);
        n4 = CC * C3 / 4;
        to_half_kernel<<<(n4 + 255) / 256, 256>>>(w_qkv, d_wqkv, n4);
        n4 = CC * CC / 4;
        to_half_kernel<<<(n4 + 255) / 256, 256>>>(w_proj, d_wproj, n4);
    }

    dim3 g1(C3 / BN, MROWS / BM);   // 18 x 196
    gemm_qkv_k<<<g1, 256, GEMM_SMEM_BYTES>>>(b_qkv);

    attn_kernel<<<NHEADS_TOTAL, 512, ATTN_SMEM_BYTES>>>(rph, rpw);

    dim3 g2(CC / BN, MROWS / BM);   // 6 x 196
    gemm_proj_k<<<g2, 256, GEMM_SMEM_BYTES>>>(b_proj, out);
}

// round 13
// speedup vs baseline: 1.0001x; 1.0001x over previous
#include <cuda_runtime.h>
#include <cuda_fp16.h>
#include <mma.h>
#include <cstddef>
#include <cstdint>

using namespace nvcuda;

// Problem constants
#define BATCH 128
#define HH 14
#define WW 14
#define CC 768
#define NHEAD 12
#define HDIM 64
#define HWSZ 196          // 14*14
#define C3 2304           // 3*C
#define MROWS 25088       // BATCH*HWSZ
#define NHEADS_TOTAL 1536 // BATCH*NHEAD

#define LOG2E 1.442695040888963f

// Scratch buffers (device globals: no allocation allowed)
__device__ float  g_qkv[(size_t)MROWS * C3];  // qkv GEMM out (fp32)
__device__ __half g_att[(size_t)MROWS * CC];  // attention out (fp16)
__device__ __half g_x[(size_t)MROWS * CC];    // x (fp16)
__device__ __half g_wqkv[(size_t)CC * C3];    // w_qkv (fp16)
__device__ __half g_wproj[(size_t)CC * CC];   // w_proj (fp16)

// ---------------------------------------------------------------------------
// helpers
// ---------------------------------------------------------------------------
__global__ void to_half_kernel(const float* __restrict__ in,
                               __half* __restrict__ out, int n4)
{
    int i = blockIdx.x * blockDim.x + threadIdx.x;
    if (i < n4) {
        float4 v = ((const float4*)in)[i];
        __half2 a = __floats2half2_rn(v.x, v.y);
        __half2 b = __floats2half2_rn(v.z, v.w);
        uint2 pk;
        pk.x = *(uint32_t*)&a;
        pk.y = *(uint32_t*)&b;
        ((uint2*)out)[i] = pk;
    }
}

// Packed 2^x for two fp32 args via f16x2 MUFU (1 EX2 for 2 values).
__device__ __forceinline__ float2 exp2_2(float a, float b) {
    uint32_t h, e;
    asm("cvt.rn.f16x2.f32 %0, %1, %2;" : "=r"(h) : "f"(b), "f"(a)); // hi=b, lo=a
    asm("ex2.approx.f16x2 %0, %1;" : "=r"(e) : "r"(h));
    float2 r;
    asm("{.reg .f16 lo, hi;\n\t"
        "mov.b32 {lo, hi}, %2;\n\t"
        "cvt.f32.f16 %0, lo;\n\t"
        "cvt.f32.f16 %1, hi;}"
        : "=f"(r.x), "=f"(r.y) : "r"(e));
    return r;
}

__device__ __forceinline__ void cpa16(void* s, const void* g) {
    uint32_t sa = (uint32_t)__cvta_generic_to_shared(s);
    asm volatile("cp.async.cg.shared.global [%0], [%1], 16;\n" ::"r"(sa), "l"(g));
}
__device__ __forceinline__ void cpa_commit() {
    asm volatile("cp.async.commit_group;\n" ::);
}
template <int N>
__device__ __forceinline__ void cpa_wait() {
    asm volatile("cp.async.wait_group %0;\n" ::"n"(N));
}

// ---------------------------------------------------------------------------
// Pipelined fp16 GEMM: C(fp32) = A(MxK,f16) @ B(KxN,f16) + bias(fp32)
// BM=BN=128, BK=64, wmma m16n16k16, 2-stage cp.async, 256 thr, 2 CTA/SM.
// Direct fp32 store_matrix_sync epilogue (fast tail).
// ---------------------------------------------------------------------------
#define BM 128
#define BN 128
#define BK 64
#define BSTR 136   // halves per B row: 128 + 8 pad
#define ASTRH 72   // halves per A row: 64 + 8 pad

#define GEMM_SMEM_BYTES ((2 * BM * ASTRH + 2 * BK * BSTR) * 2 + 16 * BSTR * 4)

__device__ __forceinline__ void gemm_body(
    const __half* __restrict__ A, const __half* __restrict__ Bm,
    const float* __restrict__ bias, float* __restrict__ Cout,
    int M, int N, int K)
{
    extern __shared__ char smraw[];
    __half* As = (__half*)smraw;                       // 2 x BM x ASTRH
    __half* Bs = As + 2 * BM * ASTRH;                  // 2 x BK x BSTR
    float* biasT = (float*)(Bs + 2 * BK * BSTR);       // 16 x BSTR fp32

    const int tid = threadIdx.x;
    const int m0 = blockIdx.y * BM;
    const int n0 = blockIdx.x * BN;

    for (int i = tid; i < 16 * BN; i += 256) {
        int rr = i >> 7, cc = i & 127;
        biasT[rr * BSTR + cc] = bias[n0 + cc];
    }
    __syncthreads();

    const int w  = tid >> 5;
    const int wm = w >> 2;
    const int wn = w & 3;

    wmma::fragment<wmma::accumulator, 16, 16, 16, float> acc[4][2];
#pragma unroll
    for (int i = 0; i < 4; i++)
#pragma unroll
        for (int j = 0; j < 2; j++)
            wmma::load_matrix_sync(acc[i][j], &biasT[wn * 32 + j * 16], BSTR,
                                   wmma::mem_row_major);

    const int arow = tid >> 3, ac8 = (tid & 7) * 8;
    const int brow = tid >> 4, bc8 = (tid & 15) * 8;

    const int T = K / BK;

    {
        const __half* ag = &A[(size_t)(m0 + arow) * K + ac8];
        const __half* bg = &Bm[(size_t)brow * N + n0 + bc8];
#pragma unroll
        for (int p = 0; p < 4; p++)
            cpa16(&As[(arow + p * 32) * ASTRH + ac8], ag + (size_t)(p * 32) * K);
#pragma unroll
        for (int p = 0; p < 4; p++)
            cpa16(&Bs[(brow + p * 16) * BSTR + bc8], bg + (size_t)(p * 16) * N);
        cpa_commit();
    }

    for (int t = 0; t < T; t++) {
        if (t + 1 < T) {
            const int st = (t + 1) & 1;
            const int kt = (t + 1) * BK;
            const __half* ag = &A[(size_t)(m0 + arow) * K + kt + ac8];
            const __half* bg = &Bm[(size_t)(kt + brow) * N + n0 + bc8];
            __half* asd = &As[st * BM * ASTRH];
            __half* bsd = &Bs[st * BK * BSTR];
#pragma unroll
            for (int p = 0; p < 4; p++)
                cpa16(&asd[(arow + p * 32) * ASTRH + ac8], ag + (size_t)(p * 32) * K);
#pragma unroll
            for (int p = 0; p < 4; p++)
                cpa16(&bsd[(brow + p * 16) * BSTR + bc8], bg + (size_t)(p * 16) * N);
            cpa_commit();
            cpa_wait<1>();
        } else {
            cpa_wait<0>();
        }
        __syncthreads();

        const __half* asrc = &As[(t & 1) * BM * ASTRH];
        const __half* bsrc = &Bs[(t & 1) * BK * BSTR];

#pragma unroll
        for (int kk = 0; kk < BK; kk += 16) {
            wmma::fragment<wmma::matrix_a, 16, 16, 16, __half, wmma::row_major> af[4];
            wmma::fragment<wmma::matrix_b, 16, 16, 16, __half, wmma::row_major> bf[2];
#pragma unroll
            for (int i = 0; i < 4; i++)
                wmma::load_matrix_sync(af[i], &asrc[(wm * 64 + i * 16) * ASTRH + kk], ASTRH);
#pragma unroll
            for (int j = 0; j < 2; j++)
                wmma::load_matrix_sync(bf[j], &bsrc[kk * BSTR + wn * 32 + j * 16], BSTR);
#pragma unroll
            for (int i = 0; i < 4; i++)
#pragma unroll
                for (int j = 0; j < 2; j++)
                    wmma::mma_sync(acc[i][j], af[i], bf[j], acc[i][j]);
        }
        __syncthreads();
    }

#pragma unroll
    for (int i = 0; i < 4; i++)
#pragma unroll
        for (int j = 0; j < 2; j++)
            wmma::store_matrix_sync(
                Cout + (size_t)(m0 + wm * 64 + i * 16) * N + n0 + wn * 32 + j * 16,
                acc[i][j], N, wmma::mem_row_major);
}

__global__ __launch_bounds__(256, 2) void gemm_qkv_k(const float* __restrict__ bias)
{
    gemm_body(g_x, g_wqkv, bias, g_qkv, MROWS, C3, CC);
}

__global__ __launch_bounds__(256, 2) void gemm_proj_k(
    const float* __restrict__ bias, float* __restrict__ C)
{
    gemm_body(g_att, g_wproj, bias, C, MROWS, CC, CC);
}

// ---------------------------------------------------------------------------
// Tensorized fp16 attention: one CTA per (batch, head), 512 threads (16 warps).
// K (rows 0..195) + rel tables (rows 224..250 Rh, 256..282 Rw) in fp16 smem
// (converted from fp32 g_qkv during staging); V resident; queries in 4 blocks
// of 64 rows. QK^T wmma -> log2-softmax (packed f16 EX2, norm folded into
// fp16 P) -> PV wmma -> fp16 out.
// ---------------------------------------------------------------------------
#define AKSTR 72      // halves per K/V/Q row (64 + 8 pad)
#define SSTRF 296     // fp32 S row stride
#define PSTR 232      // halves per P row

#define ASM_K (288 * AKSTR)
#define ASM_V (224 * AKSTR)
#define ASM_Q (64 * AKSTR)
#define ASM_P (64 * PSTR)
#define ASM_S (64 * SSTRF)
#define ATTN_SMEM_BYTES ((ASM_K + ASM_V + ASM_Q + ASM_P) * 2 + ASM_S * 4)

__global__ __launch_bounds__(512) void attn_kernel(
    const float* __restrict__ rph, const float* __restrict__ rpw)
{
    extern __shared__ char smraw[];
    __half* kS = (__half*)smraw;
    __half* vS = kS + ASM_K;
    __half* qS = vS + ASM_V;
    __half* pS = qS + ASM_Q;
    float*  sS = (float*)(pS + ASM_P);

    const int tid = threadIdx.x;
    const int wid = tid >> 5, lane = tid & 31;
    const int head = blockIdx.x;
    const int b = head / NHEAD;
    const int h = head % NHEAD;

    const float* gbase = g_qkv + (size_t)b * HWSZ * C3 + h * HDIM;

    // Zero pad rows: kS 196..223, 251..255, 283..287; vS 196..223
    {
        const uint4 z = make_uint4(0, 0, 0, 0);
        for (int i = tid; i < 28 * 9; i += 512) ((uint4*)(kS + 196 * AKSTR))[i] = z;
        for (int i = tid; i < 5 * 9; i += 512) {
            ((uint4*)(kS + 251 * AKSTR))[i] = z;
            ((uint4*)(kS + 283 * AKSTR))[i] = z;
        }
        for (int i = tid; i < 28 * 9; i += 512) ((uint4*)(vS + 196 * AKSTR))[i] = z;
    }
    // Stage K, V from fp32 with inline fp16 conversion (coalesced float2 LDG)
    for (int i = tid; i < HWSZ * 32; i += 512) {
        int j = i >> 5, c2 = (i & 31) * 2;
        const float* p = gbase + (size_t)j * C3 + c2;
        float2 kv = *(const float2*)(p + 768);
        float2 vv = *(const float2*)(p + 1536);
        *(__half2*)(kS + j * AKSTR + c2) = __floats2half2_rn(kv.x, kv.y);
        *(__half2*)(vS + j * AKSTR + c2) = __floats2half2_rn(vv.x, vv.y);
    }
    // Rel tables (fp32 -> fp16) as extra key rows
    for (int i = tid; i < 27 * HDIM; i += 512) {
        int r = i >> 6, d = i & 63;
        kS[(224 + r) * AKSTR + d] = __float2half(rph[i]);
        kS[(256 + r) * AKSTR + d] = __float2half(rpw[i]);
    }
    __syncthreads();

    for (int blk = 0; blk < 4; blk++) {
        const int r0 = blk * 64;

        // --- Stage Q block (64 x 64 fp16 from fp32), zero invalid rows ---
        for (int i = tid; i < 64 * 32; i += 512) {
            int r = i >> 5, c2 = (i & 31) * 2;
            __half2 v = __floats2half2_rn(0.f, 0.f);
            if (r0 + r < HWSZ) {
                float2 q = *(const float2*)(gbase + (size_t)(r0 + r) * C3 + c2);
                v = __floats2half2_rn(q.x, q.y);
            }
            *(__half2*)(qS + r * AKSTR + c2) = v;
        }
        __syncthreads();

        // --- QK^T (+rel cols): 4x18 tiles of 16x16, k=64 ---
        for (int t = wid; t < 72; t += 16) {
            const int mt = t / 18, nt = t % 18;
            wmma::fragment<wmma::accumulator, 16, 16, 16, float> acc;
            wmma::fill_fragment(acc, 0.f);
#pragma unroll
            for (int ks = 0; ks < 4; ks++) {
                wmma::fragment<wmma::matrix_a, 16, 16, 16, __half, wmma::row_major> af;
                wmma::fragment<wmma::matrix_b, 16, 16, 16, __half, wmma::col_major> bf;
                wmma::load_matrix_sync(af, qS + mt * 16 * AKSTR + ks * 16, AKSTR);
                wmma::load_matrix_sync(bf, kS + nt * 16 * AKSTR + ks * 16, AKSTR);
                wmma::mma_sync(acc, af, bf, acc);
            }
            wmma::store_matrix_sync(sS + mt * 16 * SSTRF + nt * 16, acc, SSTRF,
                                    wmma::mem_row_major);
        }
        __syncthreads();

        // --- Softmax (8 threads/row, 28 cols each), P = e/sum in fp16 ---
        {
            const int r = tid >> 3, sub = tid & 7;
            const int qr = r0 + r;
            const int qv = (qr < HWSZ) ? qr : 0;
            const int hq = qv / 14, wq = qv % 14;
            const float* srow = sS + r * SSTRF;
            float e[28];
            float lsum = 0.f;
#pragma unroll
            for (int i = 0; i < 28; i += 2) {
                float s01[2];
#pragma unroll
                for (int u = 0; u < 2; u++) {
                    int j = sub + (i + u) * 8;
                    if (j < HWSZ) {
                        int i1 = hq - j / 14 + 13;
                        int i2 = wq - j % 14 + 13;
                        s01[u] = (srow[j] * 0.125f + srow[224 + i1] + srow[256 + i2])
                                 * LOG2E;
                    } else {
                        s01[u] = -30.0f;  // exp2 -> 0 in f16
                    }
                }
                float2 ee = exp2_2(s01[0], s01[1]);
                e[i] = ee.x;
                e[i + 1] = ee.y;
                lsum += ee.x + ee.y;
            }
#pragma unroll
            for (int o = 4; o > 0; o >>= 1)
                lsum += __shfl_xor_sync(0xffffffffu, lsum, o);
            const float inv = 1.f / lsum;
            __half* prow = pS + r * PSTR;
#pragma unroll
            for (int i = 0; i < 28; i++)
                prow[sub + i * 8] = __float2half(e[i] * inv);
        }
        __syncthreads();

        // --- PV: 4x4 tiles of 16x16, k=224 (14 steps); O -> sS ---
        {
            const int mt = wid >> 2, nt = wid & 3;
            wmma::fragment<wmma::accumulator, 16, 16, 16, float> acc;
            wmma::fill_fragment(acc, 0.f);
#pragma unroll
            for (int ks = 0; ks < 14; ks++) {
                wmma::fragment<wmma::matrix_a, 16, 16, 16, __half, wmma::row_major> af;
                wmma::fragment<wmma::matrix_b, 16, 16, 16, __half, wmma::row_major> bf;
                wmma::load_matrix_sync(af, pS + mt * 16 * PSTR + ks * 16, PSTR);
                wmma::load_matrix_sync(bf, vS + ks * 16 * AKSTR + nt * 16, AKSTR);
                wmma::mma_sync(acc, af, bf, acc);
            }
            wmma::store_matrix_sync(sS + mt * 16 * SSTRF + nt * 16, acc, SSTRF,
                                    wmma::mem_row_major);
        }
        __syncthreads();

        // --- Store valid O rows (fp16) ---
        {
            const int nv = (HWSZ - r0 < 64) ? (HWSZ - r0) : 64;
            __half* gout = g_att + ((size_t)b * HWSZ + r0) * CC + h * HDIM;
            for (int idx = tid; idx < 64 * 32; idx += 512) {
                int r = idx >> 5, c2 = idx & 31;
                if (r < nv) {
                    __half2 v = __floats2half2_rn(sS[r * SSTRF + c2 * 2],
                                                  sS[r * SSTRF + c2 * 2 + 1]);
                    *(__half2*)(gout + (size_t)r * CC + c2 * 2) = v;
                }
            }
        }
        __syncthreads();
    }
}

// ---------------------------------------------------------------------------
extern "C" void kernel_launch(void* const* d_in, const int* in_sizes, int n_in,
                              void* d_out, int out_size)
{
    const float* x      = (const float*)d_in[0]; // (25088, 768)
    const float* w_qkv  = (const float*)d_in[1]; // (768, 2304)
    const float* b_qkv  = (const float*)d_in[2]; // (2304,)
    const float* rph    = (const float*)d_in[3]; // (27, 64)
    const float* rpw    = (const float*)d_in[4]; // (27, 64)
    const float* w_proj = (const float*)d_in[5]; // (768, 768)
    const float* b_proj = (const float*)d_in[6]; // (768,)
    float* out = (float*)d_out;                  // (25088, 768)

    __half *d_x, *d_wqkv, *d_wproj;
    cudaGetSymbolAddress((void**)&d_x, g_x);
    cudaGetSymbolAddress((void**)&d_wqkv, g_wqkv);
    cudaGetSymbolAddress((void**)&d_wproj, g_wproj);

    cudaFuncSetAttribute(gemm_qkv_k,
                         cudaFuncAttributeMaxDynamicSharedMemorySize,
                         GEMM_SMEM_BYTES);
    cudaFuncSetAttribute(gemm_proj_k,
                         cudaFuncAttributeMaxDynamicSharedMemorySize,
                         GEMM_SMEM_BYTES);
    cudaFuncSetAttribute(attn_kernel,
                         cudaFuncAttributeMaxDynamicSharedMemorySize,
                         ATTN_SMEM_BYTES);

    // Convert GEMM inputs to fp16
    {
        int n4 = MROWS * CC / 4;
        to_half_kernel<<<(n4 + 255) / 256, 256>>>(x, d_x, n4);
        n4 = CC * C3 / 4;
        to_half_kernel<<<(n4 + 255) / 256, 256>>>(w_qkv, d_wqkv, n4);
        n4 = CC * CC / 4;
        to_half_kernel<<<(n4 + 255) / 256, 256>>>(w_proj, d_wproj, n4);
    }

    dim3 g1(C3 / BN, MROWS / BM);   // 18 x 196
    gemm_qkv_k<<<g1, 256, GEMM_SMEM_BYTES>>>(b_qkv);

    attn_kernel<<<NHEADS_TOTAL, 512, ATTN_SMEM_BYTES>>>(rph, rpw);

    dim3 g2(CC / BN, MROWS / BM);   // 6 x 196
    gemm_proj_k<<<g2, 256, GEMM_SMEM_BYTES>>>(b_proj, out);
}

// round 14
// speedup vs baseline: 1.1999x; 1.1998x over previous
#include <cuda_runtime.h>
#include <cuda_fp16.h>
#include <mma.h>
#include <cstddef>
#include <cstdint>

using namespace nvcuda;

// Problem constants
#define BATCH 128
#define HH 14
#define WW 14
#define CC 768
#define NHEAD 12
#define HDIM 64
#define HWSZ 196          // 14*14
#define C3 2304           // 3*C
#define MROWS 25088       // BATCH*HWSZ
#define NHEADS_TOTAL 1536 // BATCH*NHEAD

#define LOG2E 1.442695040888963f

// Scratch buffers (device globals: no allocation allowed)
__device__ __half g_qkv[(size_t)MROWS * C3];  // qkv GEMM out (fp16)
__device__ __half g_att[(size_t)MROWS * CC];  // attention out (fp16)
__device__ __half g_x[(size_t)MROWS * CC];    // x (fp16)
__device__ __half g_wqkv[(size_t)CC * C3];    // w_qkv (fp16)
__device__ __half g_wproj[(size_t)CC * CC];   // w_proj (fp16)

// ---------------------------------------------------------------------------
// helpers
// ---------------------------------------------------------------------------
__global__ void to_half_kernel(const float* __restrict__ in,
                               __half* __restrict__ out, int n4)
{
    int i = blockIdx.x * blockDim.x + threadIdx.x;
    if (i < n4) {
        float4 v = ((const float4*)in)[i];
        __half2 a = __floats2half2_rn(v.x, v.y);
        __half2 b = __floats2half2_rn(v.z, v.w);
        uint2 pk;
        pk.x = *(uint32_t*)&a;
        pk.y = *(uint32_t*)&b;
        ((uint2*)out)[i] = pk;
    }
}

// Packed 2^x for two fp32 args via f16x2 MUFU (1 EX2 for 2 values).
__device__ __forceinline__ float2 exp2_2(float a, float b) {
    uint32_t h, e;
    asm("cvt.rn.f16x2.f32 %0, %1, %2;" : "=r"(h) : "f"(b), "f"(a)); // hi=b, lo=a
    asm("ex2.approx.f16x2 %0, %1;" : "=r"(e) : "r"(h));
    float2 r;
    asm("{.reg .f16 lo, hi;\n\t"
        "mov.b32 {lo, hi}, %2;\n\t"
        "cvt.f32.f16 %0, lo;\n\t"
        "cvt.f32.f16 %1, hi;}"
        : "=f"(r.x), "=f"(r.y) : "r"(e));
    return r;
}

__device__ __forceinline__ void cpa16(void* s, const void* g) {
    uint32_t sa = (uint32_t)__cvta_generic_to_shared(s);
    asm volatile("cp.async.cg.shared.global [%0], [%1], 16;\n" ::"r"(sa), "l"(g));
}
__device__ __forceinline__ void cpa_commit() {
    asm volatile("cp.async.commit_group;\n" ::);
}
template <int N>
__device__ __forceinline__ void cpa_wait() {
    asm volatile("cp.async.wait_group %0;\n" ::"n"(N));
}

// ---------------------------------------------------------------------------
// Pipelined fp16 GEMM: C = A(MxK,f16) @ B(KxN,f16) + bias(fp32)
// BM=BN=128, BK=64, wmma m16n16k16, 2-stage cp.async, 256 thr, 2 CTA/SM.
// HALF_OUT: block-staged fp16 epilogue through reused mainloop smem
// (parallel store_matrix_sync -> one sync -> coalesced half2 stores).
// ---------------------------------------------------------------------------
#define BM 128
#define BN 128
#define BK 64
#define BSTR 136   // halves per B row: 128 + 8 pad
#define ASTRH 72   // halves per A row: 64 + 8 pad
#define CTSTR 132  // fp32 epilogue tile stride (128 + 4 pad)

#define GEMM_SMEM_BYTES ((2 * BM * ASTRH + 2 * BK * BSTR) * 2 + 16 * BSTR * 4)

template <bool HALF_OUT>
__device__ __forceinline__ void gemm_body(
    const __half* __restrict__ A, const __half* __restrict__ Bm,
    const float* __restrict__ bias, void* __restrict__ Cout,
    int M, int N, int K)
{
    extern __shared__ char smraw[];
    __half* As = (__half*)smraw;                       // 2 x BM x ASTRH
    __half* Bs = As + 2 * BM * ASTRH;                  // 2 x BK x BSTR
    float* biasT = (float*)(Bs + 2 * BK * BSTR);       // 16 x BSTR fp32

    const int tid = threadIdx.x;
    const int m0 = blockIdx.y * BM;
    const int n0 = blockIdx.x * BN;

    for (int i = tid; i < 16 * BN; i += 256) {
        int rr = i >> 7, cc = i & 127;
        biasT[rr * BSTR + cc] = bias[n0 + cc];
    }
    __syncthreads();

    const int w  = tid >> 5;
    const int wm = w >> 2;
    const int wn = w & 3;

    wmma::fragment<wmma::accumulator, 16, 16, 16, float> acc[4][2];
#pragma unroll
    for (int i = 0; i < 4; i++)
#pragma unroll
        for (int j = 0; j < 2; j++)
            wmma::load_matrix_sync(acc[i][j], &biasT[wn * 32 + j * 16], BSTR,
                                   wmma::mem_row_major);

    const int arow = tid >> 3, ac8 = (tid & 7) * 8;
    const int brow = tid >> 4, bc8 = (tid & 15) * 8;

    const int T = K / BK;

    {
        const __half* ag = &A[(size_t)(m0 + arow) * K + ac8];
        const __half* bg = &Bm[(size_t)brow * N + n0 + bc8];
#pragma unroll
        for (int p = 0; p < 4; p++)
            cpa16(&As[(arow + p * 32) * ASTRH + ac8], ag + (size_t)(p * 32) * K);
#pragma unroll
        for (int p = 0; p < 4; p++)
            cpa16(&Bs[(brow + p * 16) * BSTR + bc8], bg + (size_t)(p * 16) * N);
        cpa_commit();
    }

    for (int t = 0; t < T; t++) {
        if (t + 1 < T) {
            const int st = (t + 1) & 1;
            const int kt = (t + 1) * BK;
            const __half* ag = &A[(size_t)(m0 + arow) * K + kt + ac8];
            const __half* bg = &Bm[(size_t)(kt + brow) * N + n0 + bc8];
            __half* asd = &As[st * BM * ASTRH];
            __half* bsd = &Bs[st * BK * BSTR];
#pragma unroll
            for (int p = 0; p < 4; p++)
                cpa16(&asd[(arow + p * 32) * ASTRH + ac8], ag + (size_t)(p * 32) * K);
#pragma unroll
            for (int p = 0; p < 4; p++)
                cpa16(&bsd[(brow + p * 16) * BSTR + bc8], bg + (size_t)(p * 16) * N);
            cpa_commit();
            cpa_wait<1>();
        } else {
            cpa_wait<0>();
        }
        __syncthreads();

        const __half* asrc = &As[(t & 1) * BM * ASTRH];
        const __half* bsrc = &Bs[(t & 1) * BK * BSTR];

#pragma unroll
        for (int kk = 0; kk < BK; kk += 16) {
            wmma::fragment<wmma::matrix_a, 16, 16, 16, __half, wmma::row_major> af[4];
            wmma::fragment<wmma::matrix_b, 16, 16, 16, __half, wmma::row_major> bf[2];
#pragma unroll
            for (int i = 0; i < 4; i++)
                wmma::load_matrix_sync(af[i], &asrc[(wm * 64 + i * 16) * ASTRH + kk], ASTRH);
#pragma unroll
            for (int j = 0; j < 2; j++)
                wmma::load_matrix_sync(bf[j], &bsrc[kk * BSTR + wn * 32 + j * 16], BSTR);
#pragma unroll
            for (int i = 0; i < 4; i++)
#pragma unroll
                for (int j = 0; j < 2; j++)
                    wmma::mma_sync(acc[i][j], af[i], bf[j], acc[i][j]);
        }
        __syncthreads();
    }

    if (HALF_OUT) {
        // Block-staged fp16 epilogue: reuse mainloop smem as 128x132 fp32 tile.
        float* ct = (float*)smraw;  // 128*132*4 = 67.6 KB < As+Bs region
#pragma unroll
        for (int i = 0; i < 4; i++)
#pragma unroll
            for (int j = 0; j < 2; j++)
                wmma::store_matrix_sync(
                    ct + (wm * 64 + i * 16) * CTSTR + wn * 32 + j * 16,
                    acc[i][j], CTSTR, wmma::mem_row_major);
        __syncthreads();
        __half* Ch = (__half*)Cout;
#pragma unroll
        for (int p = 0; p < 32; p++) {
            const int idx = tid + p * 256;        // 0..8191
            const int r = idx >> 6, c2 = idx & 63;
            __half2 v = __floats2half2_rn(ct[r * CTSTR + c2 * 2],
                                          ct[r * CTSTR + c2 * 2 + 1]);
            *(__half2*)(Ch + (size_t)(m0 + r) * N + n0 + c2 * 2) = v;
        }
    } else {
#pragma unroll
        for (int i = 0; i < 4; i++)
#pragma unroll
            for (int j = 0; j < 2; j++)
                wmma::store_matrix_sync(
                    (float*)Cout + (size_t)(m0 + wm * 64 + i * 16) * N
                        + n0 + wn * 32 + j * 16,
                    acc[i][j], N, wmma::mem_row_major);
    }
}

__global__ __launch_bounds__(256, 2) void gemm_qkv_k(const float* __restrict__ bias)
{
    gemm_body<true>(g_x, g_wqkv, bias, g_qkv, MROWS, C3, CC);
}

__global__ __launch_bounds__(256, 2) void gemm_proj_k(
    const float* __restrict__ bias, float* __restrict__ C)
{
    gemm_body<false>(g_att, g_wproj, bias, C, MROWS, CC, CC);
}

// ---------------------------------------------------------------------------
// Tensorized fp16 attention (R11 version): one CTA per (batch, head),
// 512 threads (16 warps). K (rows 0..195) + rel tables (rows 224..250 Rh,
// 256..282 Rw) in fp16 smem via cp.async from fp16 g_qkv; V resident;
// queries in 4 blocks of 64 rows. QK^T wmma -> log2-softmax (packed f16 EX2,
// norm folded into fp16 P) -> PV wmma -> fp16 out.
// ---------------------------------------------------------------------------
#define AKSTR 72      // halves per K/V/Q row (64 + 8 pad)
#define SSTRF 296     // fp32 S row stride
#define PSTR 232      // halves per P row

#define ASM_K (288 * AKSTR)
#define ASM_V (224 * AKSTR)
#define ASM_Q (64 * AKSTR)
#define ASM_P (64 * PSTR)
#define ASM_S (64 * SSTRF)
#define ATTN_SMEM_BYTES ((ASM_K + ASM_V + ASM_Q + ASM_P) * 2 + ASM_S * 4)

__global__ __launch_bounds__(512) void attn_kernel(
    const float* __restrict__ rph, const float* __restrict__ rpw)
{
    extern __shared__ char smraw[];
    __half* kS = (__half*)smraw;
    __half* vS = kS + ASM_K;
    __half* qS = vS + ASM_V;
    __half* pS = qS + ASM_Q;
    float*  sS = (float*)(pS + ASM_P);

    const int tid = threadIdx.x;
    const int wid = tid >> 5;
    const int head = blockIdx.x;
    const int b = head / NHEAD;
    const int h = head % NHEAD;

    const __half* gbase = g_qkv + (size_t)b * HWSZ * C3 + h * HDIM;

    // Zero pad rows: kS 196..223, 251..255, 283..287; vS 196..223
    {
        const uint4 z = make_uint4(0, 0, 0, 0);
        for (int i = tid; i < 28 * 9; i += 512) ((uint4*)(kS + 196 * AKSTR))[i] = z;
        for (int i = tid; i < 5 * 9; i += 512) {
            ((uint4*)(kS + 251 * AKSTR))[i] = z;
            ((uint4*)(kS + 283 * AKSTR))[i] = z;
        }
        for (int i = tid; i < 28 * 9; i += 512) ((uint4*)(vS + 196 * AKSTR))[i] = z;
    }
    // Stage K, V via cp.async (fp16 source)
    for (int i = tid; i < HWSZ * 8; i += 512) {
        int j = i >> 3, seg = (i & 7) * 8;
        cpa16(kS + j * AKSTR + seg, gbase + (size_t)j * C3 + 768 + seg);
        cpa16(vS + j * AKSTR + seg, gbase + (size_t)j * C3 + 1536 + seg);
    }
    cpa_commit();
    // Rel tables (fp32 -> fp16) as extra key rows
    for (int i = tid; i < 27 * HDIM; i += 512) {
        int r = i >> 6, d = i & 63;
        kS[(224 + r) * AKSTR + d] = __float2half(rph[i]);
        kS[(256 + r) * AKSTR + d] = __float2half(rpw[i]);
    }
    cpa_wait<0>();
    __syncthreads();

    for (int blk = 0; blk < 4; blk++) {
        const int r0 = blk * 64;

        // --- Stage Q block (64 x 64 fp16), zero invalid rows ---
        for (int i = tid; i < 64 * 8; i += 512) {
            int r = i >> 3, seg = (i & 7) * 8;
            uint4 v = make_uint4(0, 0, 0, 0);
            if (r0 + r < HWSZ)
                v = *(const uint4*)(gbase + (size_t)(r0 + r) * C3 + seg);
            *(uint4*)(qS + r * AKSTR + seg) = v;
        }
        __syncthreads();

        // --- QK^T (+rel cols): 4x18 tiles of 16x16, k=64 ---
        for (int t = wid; t < 72; t += 16) {
            const int mt = t / 18, nt = t % 18;
            wmma::fragment<wmma::accumulator, 16, 16, 16, float> acc;
            wmma::fill_fragment(acc, 0.f);
#pragma unroll
            for (int ks = 0; ks < 4; ks++) {
                wmma::fragment<wmma::matrix_a, 16, 16, 16, __half, wmma::row_major> af;
                wmma::fragment<wmma::matrix_b, 16, 16, 16, __half, wmma::col_major> bf;
                wmma::load_matrix_sync(af, qS + mt * 16 * AKSTR + ks * 16, AKSTR);
                wmma::load_matrix_sync(bf, kS + nt * 16 * AKSTR + ks * 16, AKSTR);
                wmma::mma_sync(acc, af, bf, acc);
            }
            wmma::store_matrix_sync(sS + mt * 16 * SSTRF + nt * 16, acc, SSTRF,
                                    wmma::mem_row_major);
        }
        __syncthreads();

        // --- Softmax (8 threads/row, 28 cols each), P = e/sum in fp16 ---
        {
            const int r = tid >> 3, sub = tid & 7;
            const int qr = r0 + r;
            const int qv = (qr < HWSZ) ? qr : 0;
            const int hq = qv / 14, wq = qv % 14;
            const float* srow = sS + r * SSTRF;
            float e[28];
            float lsum = 0.f;
#pragma unroll
            for (int i = 0; i < 28; i += 2) {
                float s01[2];
#pragma unroll
                for (int u = 0; u < 2; u++) {
                    int j = sub + (i + u) * 8;
                    if (j < HWSZ) {
                        int i1 = hq - j / 14 + 13;
                        int i2 = wq - j % 14 + 13;
                        s01[u] = (srow[j] * 0.125f + srow[224 + i1] + srow[256 + i2])
                                 * LOG2E;
                    } else {
                        s01[u] = -30.0f;  // exp2 -> 0 in f16
                    }
                }
                float2 ee = exp2_2(s01[0], s01[1]);
                e[i] = ee.x;
                e[i + 1] = ee.y;
                lsum += ee.x + ee.y;
            }
#pragma unroll
            for (int o = 4; o > 0; o >>= 1)
                lsum += __shfl_xor_sync(0xffffffffu, lsum, o);
            const float inv = 1.f / lsum;
            __half* prow = pS + r * PSTR;
#pragma unroll
            for (int i = 0; i < 28; i++)
                prow[sub + i * 8] = __float2half(e[i] * inv);
        }
        __syncthreads();

        // --- PV: 4x4 tiles of 16x16, k=224 (14 steps); O -> sS ---
        {
            const int mt = wid >> 2, nt = wid & 3;
            wmma::fragment<wmma::accumulator, 16, 16, 16, float> acc;
            wmma::fill_fragment(acc, 0.f);
#pragma unroll
            for (int ks = 0; ks < 14; ks++) {
                wmma::fragment<wmma::matrix_a, 16, 16, 16, __half, wmma::row_major> af;
                wmma::fragment<wmma::matrix_b, 16, 16, 16, __half, wmma::row_major> bf;
                wmma::load_matrix_sync(af, pS + mt * 16 * PSTR + ks * 16, PSTR);
                wmma::load_matrix_sync(bf, vS + ks * 16 * AKSTR + nt * 16, AKSTR);
                wmma::mma_sync(acc, af, bf, acc);
            }
            wmma::store_matrix_sync(sS + mt * 16 * SSTRF + nt * 16, acc, SSTRF,
                                    wmma::mem_row_major);
        }
        __syncthreads();

        // --- Store valid O rows (fp16) ---
        {
            const int nv = (HWSZ - r0 < 64) ? (HWSZ - r0) : 64;
            __half* gout = g_att + ((size_t)b * HWSZ + r0) * CC + h * HDIM;
            for (int idx = tid; idx < 64 * 32; idx += 512) {
                int r = idx >> 5, c2 = idx & 31;
                if (r < nv) {
                    __half2 v = __floats2half2_rn(sS[r * SSTRF + c2 * 2],
                                                  sS[r * SSTRF + c2 * 2 + 1]);
                    *(__half2*)(gout + (size_t)r * CC + c2 * 2) = v;
                }
            }
        }
        __syncthreads();
    }
}

// ---------------------------------------------------------------------------
extern "C" void kernel_launch(void* const* d_in, const int* in_sizes, int n_in,
                              void* d_out, int out_size)
{
    const float* x      = (const float*)d_in[0]; // (25088, 768)
    const float* w_qkv  = (const float*)d_in[1]; // (768, 2304)
    const float* b_qkv  = (const float*)d_in[2]; // (2304,)
    const float* rph    = (const float*)d_in[3]; // (27, 64)
    const float* rpw    = (const float*)d_in[4]; // (27, 64)
    const float* w_proj = (const float*)d_in[5]; // (768, 768)
    const float* b_proj = (const float*)d_in[6]; // (768,)
    float* out = (float*)d_out;                  // (25088, 768)

    __half *d_x, *d_wqkv, *d_wproj;
    cudaGetSymbolAddress((void**)&d_x, g_x);
    cudaGetSymbolAddress((void**)&d_wqkv, g_wqkv);
    cudaGetSymbolAddress((void**)&d_wproj, g_wproj);

    cudaFuncSetAttribute(gemm_qkv_k,
                         cudaFuncAttributeMaxDynamicSharedMemorySize,
                         GEMM_SMEM_BYTES);
    cudaFuncSetAttribute(gemm_proj_k,
                         cudaFuncAttributeMaxDynamicSharedMemorySize,
                         GEMM_SMEM_BYTES);
    cudaFuncSetAttribute(attn_kernel,
                         cudaFuncAttributeMaxDynamicSharedMemorySize,
                         ATTN_SMEM_BYTES);

    // Convert GEMM inputs to fp16
    {
        int n4 = MROWS * CC / 4;
        to_half_kernel<<<(n4 + 255) / 256, 256>>>(x, d_x, n4);
        n4 = CC * C3 / 4;
        to_half_kernel<<<(n4 + 255) / 256, 256>>>(w_qkv, d_wqkv, n4);
        n4 = CC * CC / 4;
        to_half_kernel<<<(n4 + 255) / 256, 256>>>(w_proj, d_wproj, n4);
    }

    dim3 g1(C3 / BN, MROWS / BM);   // 18 x 196
    gemm_qkv_k<<<g1, 256, GEMM_SMEM_BYTES>>>(b_qkv);

    attn_kernel<<<NHEADS_TOTAL, 512, ATTN_SMEM_BYTES>>>(rph, rpw);

    dim3 g2(CC / BN, MROWS / BM);   // 6 x 196
    gemm_proj_k<<<g2, 256, GEMM_SMEM_BYTES>>>(b_proj, out);
}

// round 15
// speedup vs baseline: 1.2000x; 1.0001x over previous
#include <cuda_runtime.h>
#include <cuda_fp16.h>
#include <mma.h>
#include <cstddef>
#include <cstdint>

using namespace nvcuda;

// Problem constants
#define BATCH 128
#define HH 14
#define WW 14
#define CC 768
#define NHEAD 12
#define HDIM 64
#define HWSZ 196          // 14*14
#define C3 2304           // 3*C
#define MROWS 25088       // BATCH*HWSZ
#define NHEADS_TOTAL 1536 // BATCH*NHEAD

#define LOG2E 1.442695040888963f

// Scratch buffers (device globals: no allocation allowed)
__device__ __half g_qkv[(size_t)MROWS * C3];  // qkv GEMM out (fp16)
__device__ __half g_att[(size_t)MROWS * CC];  // attention out (fp16)
__device__ __half g_x[(size_t)MROWS * CC];    // x (fp16)
__device__ __half g_wqkv[(size_t)CC * C3];    // w_qkv (fp16)
__device__ __half g_wproj[(size_t)CC * CC];   // w_proj (fp16)

// ---------------------------------------------------------------------------
// helpers
// ---------------------------------------------------------------------------
__global__ void to_half_kernel(const float* __restrict__ in,
                               __half* __restrict__ out, int n4)
{
    int i = blockIdx.x * blockDim.x + threadIdx.x;
    if (i < n4) {
        float4 v = ((const float4*)in)[i];
        __half2 a = __floats2half2_rn(v.x, v.y);
        __half2 b = __floats2half2_rn(v.z, v.w);
        uint2 pk;
        pk.x = *(uint32_t*)&a;
        pk.y = *(uint32_t*)&b;
        ((uint2*)out)[i] = pk;
    }
}

// Packed 2^x for two fp32 args via f16x2 MUFU (1 EX2 for 2 values).
__device__ __forceinline__ float2 exp2_2(float a, float b) {
    uint32_t h, e;
    asm("cvt.rn.f16x2.f32 %0, %1, %2;" : "=r"(h) : "f"(b), "f"(a)); // hi=b, lo=a
    asm("ex2.approx.f16x2 %0, %1;" : "=r"(e) : "r"(h));
    float2 r;
    asm("{.reg .f16 lo, hi;\n\t"
        "mov.b32 {lo, hi}, %2;\n\t"
        "cvt.f32.f16 %0, lo;\n\t"
        "cvt.f32.f16 %1, hi;}"
        : "=f"(r.x), "=f"(r.y) : "r"(e));
    return r;
}

__device__ __forceinline__ void cpa16(void* s, const void* g) {
    uint32_t sa = (uint32_t)__cvta_generic_to_shared(s);
    asm volatile("cp.async.cg.shared.global [%0], [%1], 16;\n" ::"r"(sa), "l"(g));
}
__device__ __forceinline__ void cpa_commit() {
    asm volatile("cp.async.commit_group;\n" ::);
}
template <int N>
__device__ __forceinline__ void cpa_wait() {
    asm volatile("cp.async.wait_group %0;\n" ::"n"(N));
}

// ---------------------------------------------------------------------------
// 3-stage pipelined fp16 GEMM: C = A(MxK,f16) @ B(KxN,f16) + bias(fp32)
// BM=BN=128, BK=64, wmma m16n16k16, 256 thr, 2 CTA/SM.
// No bias smem tile (acc init 0; bias added in staged epilogue).
// Epilogue: parallel store_matrix_sync into reused stage smem -> one sync ->
// coalesced stores (fp16 or fp32) with per-thread-resident bias float2.
// ---------------------------------------------------------------------------
#define BM 128
#define BN 128
#define BK 64
#define BSTR 136   // halves per B row: 128 + 8 pad
#define ASTRH 72   // halves per A row: 64 + 8 pad
#define CTSTR 132  // fp32 epilogue tile stride (128 + 4 pad)
#define NSTG 3
#define STG_HALVES (BM * ASTRH + BK * BSTR)   // 17920 halves = 35840 B

#define GEMM_SMEM_BYTES (NSTG * STG_HALVES * 2)   // 107520 B

template <bool HALF_OUT>
__device__ __forceinline__ void gemm_body(
    const __half* __restrict__ A, const __half* __restrict__ Bm,
    const float* __restrict__ bias, void* __restrict__ Cout,
    int M, int N, int K)
{
    extern __shared__ char smraw[];
    // Stage s occupies [s*STG_HALVES, ...): A part then B part.
    __half* smh = (__half*)smraw;

    const int tid = threadIdx.x;
    const int m0 = blockIdx.y * BM;
    const int n0 = blockIdx.x * BN;

    const int w  = tid >> 5;
    const int wm = w >> 2;
    const int wn = w & 3;

    // Per-thread epilogue bias (columns fixed by tid)
    const int ec2 = tid & 63;
    const float2 bv = *(const float2*)(bias + n0 + ec2 * 2);

    wmma::fragment<wmma::accumulator, 16, 16, 16, float> acc[4][2];
#pragma unroll
    for (int i = 0; i < 4; i++)
#pragma unroll
        for (int j = 0; j < 2; j++)
            wmma::fill_fragment(acc[i][j], 0.f);

    const int arow = tid >> 3, ac8 = (tid & 7) * 8;
    const int brow = tid >> 4, bc8 = (tid & 15) * 8;

    const int T = K / BK;

    // Prologue: stage tiles 0 and 1
#pragma unroll
    for (int pt = 0; pt < 2; pt++) {
        const int kt = pt * BK;
        const __half* ag = &A[(size_t)(m0 + arow) * K + kt + ac8];
        const __half* bg = &Bm[(size_t)(kt + brow) * N + n0 + bc8];
        __half* asd = smh + pt * STG_HALVES;
        __half* bsd = asd + BM * ASTRH;
#pragma unroll
        for (int p = 0; p < 4; p++)
            cpa16(&asd[(arow + p * 32) * ASTRH + ac8], ag + (size_t)(p * 32) * K);
#pragma unroll
        for (int p = 0; p < 4; p++)
            cpa16(&bsd[(brow + p * 16) * BSTR + bc8], bg + (size_t)(p * 16) * N);
        cpa_commit();
    }

    for (int t = 0; t < T; t++) {
        if (t + 2 < T) {
            const int st = (t + 2) % NSTG;
            const int kt = (t + 2) * BK;
            const __half* ag = &A[(size_t)(m0 + arow) * K + kt + ac8];
            const __half* bg = &Bm[(size_t)(kt + brow) * N + n0 + bc8];
            __half* asd = smh + st * STG_HALVES;
            __half* bsd = asd + BM * ASTRH;
#pragma unroll
            for (int p = 0; p < 4; p++)
                cpa16(&asd[(arow + p * 32) * ASTRH + ac8], ag + (size_t)(p * 32) * K);
#pragma unroll
            for (int p = 0; p < 4; p++)
                cpa16(&bsd[(brow + p * 16) * BSTR + bc8], bg + (size_t)(p * 16) * N);
            cpa_commit();
            cpa_wait<2>();
        } else if (t + 2 == T) {
            cpa_wait<1>();
        } else {
            cpa_wait<0>();
        }
        __syncthreads();

        const __half* asrc = smh + (t % NSTG) * STG_HALVES;
        const __half* bsrc = asrc + BM * ASTRH;

#pragma unroll
        for (int kk = 0; kk < BK; kk += 16) {
            wmma::fragment<wmma::matrix_a, 16, 16, 16, __half, wmma::row_major> af[4];
            wmma::fragment<wmma::matrix_b, 16, 16, 16, __half, wmma::row_major> bf[2];
#pragma unroll
            for (int i = 0; i < 4; i++)
                wmma::load_matrix_sync(af[i], &asrc[(wm * 64 + i * 16) * ASTRH + kk], ASTRH);
#pragma unroll
            for (int j = 0; j < 2; j++)
                wmma::load_matrix_sync(bf[j], &bsrc[kk * BSTR + wn * 32 + j * 16], BSTR);
#pragma unroll
            for (int i = 0; i < 4; i++)
#pragma unroll
                for (int j = 0; j < 2; j++)
                    wmma::mma_sync(acc[i][j], af[i], bf[j], acc[i][j]);
        }
        __syncthreads();  // all warps done with this stage before refill
    }

    // Staged epilogue: reuse stage smem as 128x132 fp32 tile (67.6 KB).
    float* ct = (float*)smraw;
#pragma unroll
    for (int i = 0; i < 4; i++)
#pragma unroll
        for (int j = 0; j < 2; j++)
            wmma::store_matrix_sync(
                ct + (wm * 64 + i * 16) * CTSTR + wn * 32 + j * 16,
                acc[i][j], CTSTR, wmma::mem_row_major);
    __syncthreads();

    if (HALF_OUT) {
        __half* Ch = (__half*)Cout;
#pragma unroll
        for (int p = 0; p < 32; p++) {
            const int idx = tid + p * 256;        // r = idx>>6, c2 = tid&63
            const int r = idx >> 6;
            __half2 v = __floats2half2_rn(ct[r * CTSTR + ec2 * 2] + bv.x,
                                          ct[r * CTSTR + ec2 * 2 + 1] + bv.y);
            *(__half2*)(Ch + (size_t)(m0 + r) * N + n0 + ec2 * 2) = v;
        }
    } else {
        float* Cf = (float*)Cout;
#pragma unroll
        for (int p = 0; p < 32; p++) {
            const int idx = tid + p * 256;
            const int r = idx >> 6;
            float2 v;
            v.x = ct[r * CTSTR + ec2 * 2] + bv.x;
            v.y = ct[r * CTSTR + ec2 * 2 + 1] + bv.y;
            *(float2*)(Cf + (size_t)(m0 + r) * N + n0 + ec2 * 2) = v;
        }
    }
}

__global__ __launch_bounds__(256, 2) void gemm_qkv_k(const float* __restrict__ bias)
{
    gemm_body<true>(g_x, g_wqkv, bias, g_qkv, MROWS, C3, CC);
}

__global__ __launch_bounds__(256, 2) void gemm_proj_k(
    const float* __restrict__ bias, float* __restrict__ C)
{
    gemm_body<false>(g_att, g_wproj, bias, C, MROWS, CC, CC);
}

// ---------------------------------------------------------------------------
// Tensorized fp16 attention: one CTA per (batch, head), 512 threads (16 warps).
// K (rows 0..195) + rel tables (rows 224..250 Rh, 256..282 Rw) in fp16 smem
// via cp.async from fp16 g_qkv; V resident; queries in 4 blocks of 64 rows.
// QK^T wmma -> log2-softmax (packed f16 EX2, norm folded into fp16 P) ->
// PV wmma -> fp16 out.
// ---------------------------------------------------------------------------
#define AKSTR 72      // halves per K/V/Q row (64 + 8 pad)
#define SSTRF 296     // fp32 S row stride
#define PSTR 232      // halves per P row

#define ASM_K (288 * AKSTR)
#define ASM_V (224 * AKSTR)
#define ASM_Q (64 * AKSTR)
#define ASM_P (64 * PSTR)
#define ASM_S (64 * SSTRF)
#define ATTN_SMEM_BYTES ((ASM_K + ASM_V + ASM_Q + ASM_P) * 2 + ASM_S * 4)

__global__ __launch_bounds__(512) void attn_kernel(
    const float* __restrict__ rph, const float* __restrict__ rpw)
{
    extern __shared__ char smraw[];
    __half* kS = (__half*)smraw;
    __half* vS = kS + ASM_K;
    __half* qS = vS + ASM_V;
    __half* pS = qS + ASM_Q;
    float*  sS = (float*)(pS + ASM_P);

    const int tid = threadIdx.x;
    const int wid = tid >> 5;
    const int head = blockIdx.x;
    const int b = head / NHEAD;
    const int h = head % NHEAD;

    const __half* gbase = g_qkv + (size_t)b * HWSZ * C3 + h * HDIM;

    // Zero pad rows: kS 196..223, 251..255, 283..287; vS 196..223
    {
        const uint4 z = make_uint4(0, 0, 0, 0);
        for (int i = tid; i < 28 * 9; i += 512) ((uint4*)(kS + 196 * AKSTR))[i] = z;
        for (int i = tid; i < 5 * 9; i += 512) {
            ((uint4*)(kS + 251 * AKSTR))[i] = z;
            ((uint4*)(kS + 283 * AKSTR))[i] = z;
        }
        for (int i = tid; i < 28 * 9; i += 512) ((uint4*)(vS + 196 * AKSTR))[i] = z;
    }
    // Stage K, V via cp.async (fp16 source)
    for (int i = tid; i < HWSZ * 8; i += 512) {
        int j = i >> 3, seg = (i & 7) * 8;
        cpa16(kS + j * AKSTR + seg, gbase + (size_t)j * C3 + 768 + seg);
        cpa16(vS + j * AKSTR + seg, gbase + (size_t)j * C3 + 1536 + seg);
    }
    cpa_commit();
    // Rel tables (fp32 -> fp16) as extra key rows
    for (int i = tid; i < 27 * HDIM; i += 512) {
        int r = i >> 6, d = i & 63;
        kS[(224 + r) * AKSTR + d] = __float2half(rph[i]);
        kS[(256 + r) * AKSTR + d] = __float2half(rpw[i]);
    }
    cpa_wait<0>();
    __syncthreads();

    for (int blk = 0; blk < 4; blk++) {
        const int r0 = blk * 64;

        // --- Stage Q block (64 x 64 fp16), zero invalid rows ---
        for (int i = tid; i < 64 * 8; i += 512) {
            int r = i >> 3, seg = (i & 7) * 8;
            uint4 v = make_uint4(0, 0, 0, 0);
            if (r0 + r < HWSZ)
                v = *(const uint4*)(gbase + (size_t)(r0 + r) * C3 + seg);
            *(uint4*)(qS + r * AKSTR + seg) = v;
        }
        __syncthreads();

        // --- QK^T (+rel cols): 4x18 tiles of 16x16, k=64 ---
        for (int t = wid; t < 72; t += 16) {
            const int mt = t / 18, nt = t % 18;
            wmma::fragment<wmma::accumulator, 16, 16, 16, float> acc;
            wmma::fill_fragment(acc, 0.f);
#pragma unroll
            for (int ks = 0; ks < 4; ks++) {
                wmma::fragment<wmma::matrix_a, 16, 16, 16, __half, wmma::row_major> af;
                wmma::fragment<wmma::matrix_b, 16, 16, 16, __half, wmma::col_major> bf;
                wmma::load_matrix_sync(af, qS + mt * 16 * AKSTR + ks * 16, AKSTR);
                wmma::load_matrix_sync(bf, kS + nt * 16 * AKSTR + ks * 16, AKSTR);
                wmma::mma_sync(acc, af, bf, acc);
            }
            wmma::store_matrix_sync(sS + mt * 16 * SSTRF + nt * 16, acc, SSTRF,
                                    wmma::mem_row_major);
        }
        __syncthreads();

        // --- Softmax (8 threads/row, 28 cols each), P = e/sum in fp16 ---
        {
            const int r = tid >> 3, sub = tid & 7;
            const int qr = r0 + r;
            const int qv = (qr < HWSZ) ? qr : 0;
            const int hq = qv / 14, wq = qv % 14;
            const float* srow = sS + r * SSTRF;
            float e[28];
            float lsum = 0.f;
#pragma unroll
            for (int i = 0; i < 28; i += 2) {
                float s01[2];
#pragma unroll
                for (int u = 0; u < 2; u++) {
                    int j = sub + (i + u) * 8;
                    if (j < HWSZ) {
                        int i1 = hq - j / 14 + 13;
                        int i2 = wq - j % 14 + 13;
                        s01[u] = (srow[j] * 0.125f + srow[224 + i1] + srow[256 + i2])
                                 * LOG2E;
                    } else {
                        s01[u] = -30.0f;  // exp2 -> 0 in f16
                    }
                }
                float2 ee = exp2_2(s01[0], s01[1]);
                e[i] = ee.x;
                e[i + 1] = ee.y;
                lsum += ee.x + ee.y;
            }
#pragma unroll
            for (int o = 4; o > 0; o >>= 1)
                lsum += __shfl_xor_sync(0xffffffffu, lsum, o);
            const float inv = 1.f / lsum;
            __half* prow = pS + r * PSTR;
#pragma unroll
            for (int i = 0; i < 28; i++)
                prow[sub + i * 8] = __float2half(e[i] * inv);
        }
        __syncthreads();

        // --- PV: 4x4 tiles of 16x16, k=224 (14 steps); O -> sS ---
        {
            const int mt = wid >> 2, nt = wid & 3;
            wmma::fragment<wmma::accumulator, 16, 16, 16, float> acc;
            wmma::fill_fragment(acc, 0.f);
#pragma unroll
            for (int ks = 0; ks < 14; ks++) {
                wmma::fragment<wmma::matrix_a, 16, 16, 16, __half, wmma::row_major> af;
                wmma::fragment<wmma::matrix_b, 16, 16, 16, __half, wmma::row_major> bf;
                wmma::load_matrix_sync(af, pS + mt * 16 * PSTR + ks * 16, PSTR);
                wmma::load_matrix_sync(bf, vS + ks * 16 * AKSTR + nt * 16, AKSTR);
                wmma::mma_sync(acc, af, bf, acc);
            }
            wmma::store_matrix_sync(sS + mt * 16 * SSTRF + nt * 16, acc, SSTRF,
                                    wmma::mem_row_major);
        }
        __syncthreads();

        // --- Store valid O rows (fp16) ---
        {
            const int nv = (HWSZ - r0 < 64) ? (HWSZ - r0) : 64;
            __half* gout = g_att + ((size_t)b * HWSZ + r0) * CC + h * HDIM;
            for (int idx = tid; idx < 64 * 32; idx += 512) {
                int r = idx >> 5, c2 = idx & 31;
                if (r < nv) {
                    __half2 v = __floats2half2_rn(sS[r * SSTRF + c2 * 2],
                                                  sS[r * SSTRF + c2 * 2 + 1]);
                    *(__half2*)(gout + (size_t)r * CC + c2 * 2) = v;
                }
            }
        }
        __syncthreads();
    }
}

// ---------------------------------------------------------------------------
extern "C" void kernel_launch(void* const* d_in, const int* in_sizes, int n_in,
                              void* d_out, int out_size)
{
    const float* x      = (const float*)d_in[0]; // (25088, 768)
    const float* w_qkv  = (const float*)d_in[1]; // (768, 2304)
    const float* b_qkv  = (const float*)d_in[2]; // (2304,)
    const float* rph    = (const float*)d_in[3]; // (27, 64)
    const float* rpw    = (const float*)d_in[4]; // (27, 64)
    const float* w_proj = (const float*)d_in[5]; // (768, 768)
    const float* b_proj = (const float*)d_in[6]; // (768,)
    float* out = (float*)d_out;                  // (25088, 768)

    __half *d_x, *d_wqkv, *d_wproj;
    cudaGetSymbolAddress((void**)&d_x, g_x);
    cudaGetSymbolAddress((void**)&d_wqkv, g_wqkv);
    cudaGetSymbolAddress((void**)&d_wproj, g_wproj);

    cudaFuncSetAttribute(gemm_qkv_k,
                         cudaFuncAttributeMaxDynamicSharedMemorySize,
                         GEMM_SMEM_BYTES);
    cudaFuncSetAttribute(gemm_proj_k,
                         cudaFuncAttributeMaxDynamicSharedMemorySize,
                         GEMM_SMEM_BYTES);
    cudaFuncSetAttribute(attn_kernel,
                         cudaFuncAttributeMaxDynamicSharedMemorySize,
                         ATTN_SMEM_BYTES);

    // Convert GEMM inputs to fp16
    {
        int n4 = MROWS * CC / 4;
        to_half_kernel<<<(n4 + 255) / 256, 256>>>(x, d_x, n4);
        n4 = CC * C3 / 4;
        to_half_kernel<<<(n4 + 255) / 256, 256>>>(w_qkv, d_wqkv, n4);
        n4 = CC * CC / 4;
        to_half_kernel<<<(n4 + 255) / 256, 256>>>(w_proj, d_wproj, n4);
    }

    dim3 g1(C3 / BN, MROWS / BM);   // 18 x 196
    gemm_qkv_k<<<g1, 256, GEMM_SMEM_BYTES>>>(b_qkv);

    attn_kernel<<<NHEADS_TOTAL, 512, ATTN_SMEM_BYTES>>>(rph, rpw);

    dim3 g2(CC / BN, MROWS / BM);   // 6 x 196
    gemm_proj_k<<<g2, 256, GEMM_SMEM_BYTES>>>(b_proj, out);
}

// round 16
// speedup vs baseline: 1.2573x; 1.0477x over previous
#include <cuda_runtime.h>
#include <cuda_fp16.h>
#include <mma.h>
#include <cstddef>
#include <cstdint>

using namespace nvcuda;

// Problem constants
#define BATCH 128
#define HH 14
#define WW 14
#define CC 768
#define NHEAD 12
#define HDIM 64
#define HWSZ 196          // 14*14
#define C3 2304           // 3*C
#define MROWS 25088       // BATCH*HWSZ
#define NHEADS_TOTAL 1536 // BATCH*NHEAD

#define LOG2E 1.442695040888963f

// Scratch buffers (device globals: no allocation allowed)
__device__ __half g_qkv[(size_t)MROWS * C3];  // qkv GEMM out (fp16)
__device__ __half g_att[(size_t)MROWS * CC];  // attention out (fp16)
__device__ __half g_x[(size_t)MROWS * CC];    // x (fp16)
__device__ __half g_wqkv[(size_t)CC * C3];    // w_qkv (fp16)
__device__ __half g_wproj[(size_t)CC * CC];   // w_proj (fp16)

// ---------------------------------------------------------------------------
// helpers
// ---------------------------------------------------------------------------
__global__ void to_half_kernel(const float* __restrict__ in,
                               __half* __restrict__ out, int n4)
{
    int i = blockIdx.x * blockDim.x + threadIdx.x;
    if (i < n4) {
        float4 v = ((const float4*)in)[i];
        __half2 a = __floats2half2_rn(v.x, v.y);
        __half2 b = __floats2half2_rn(v.z, v.w);
        uint2 pk;
        pk.x = *(uint32_t*)&a;
        pk.y = *(uint32_t*)&b;
        ((uint2*)out)[i] = pk;
    }
}

// Packed 2^x for two fp32 args via f16x2 MUFU (1 EX2 for 2 values).
__device__ __forceinline__ float2 exp2_2(float a, float b) {
    uint32_t h, e;
    asm("cvt.rn.f16x2.f32 %0, %1, %2;" : "=r"(h) : "f"(b), "f"(a)); // hi=b, lo=a
    asm("ex2.approx.f16x2 %0, %1;" : "=r"(e) : "r"(h));
    float2 r;
    asm("{.reg .f16 lo, hi;\n\t"
        "mov.b32 {lo, hi}, %2;\n\t"
        "cvt.f32.f16 %0, lo;\n\t"
        "cvt.f32.f16 %1, hi;}"
        : "=f"(r.x), "=f"(r.y) : "r"(e));
    return r;
}

__device__ __forceinline__ void cpa16(void* s, const void* g) {
    uint32_t sa = (uint32_t)__cvta_generic_to_shared(s);
    asm volatile("cp.async.cg.shared.global [%0], [%1], 16;\n" ::"r"(sa), "l"(g));
}
__device__ __forceinline__ void cpa_commit() {
    asm volatile("cp.async.commit_group;\n" ::);
}
template <int N>
__device__ __forceinline__ void cpa_wait() {
    asm volatile("cp.async.wait_group %0;\n" ::"n"(N));
}

// ---------------------------------------------------------------------------
// 3-stage pipelined fp16 GEMM, ONE barrier per K-tile.
// C = A(MxK,f16) @ B(KxN,f16) + bias(fp32). BM=BN=128, BK=64, 256 thr,
// 2 CTA/SM. Bias added in staged epilogue.
// Iter t: wait<1> (stage t arrived), barrier (all done with t-1),
//         prefetch t+2 into stage (t+2)%3 == (t-1)%3 (safe), compute t.
// ---------------------------------------------------------------------------
#define BM 128
#define BN 128
#define BK 64
#define BSTR 136   // halves per B row: 128 + 8 pad
#define ASTRH 72   // halves per A row: 64 + 8 pad
#define CTSTR 132  // fp32 epilogue tile stride (128 + 4 pad)
#define NSTG 3
#define STG_HALVES (BM * ASTRH + BK * BSTR)   // 17920 halves = 35840 B

#define GEMM_SMEM_BYTES (NSTG * STG_HALVES * 2)   // 107520 B

template <bool HALF_OUT>
__device__ __forceinline__ void gemm_body(
    const __half* __restrict__ A, const __half* __restrict__ Bm,
    const float* __restrict__ bias, void* __restrict__ Cout,
    int M, int N, int K)
{
    extern __shared__ char smraw[];
    __half* smh = (__half*)smraw;

    const int tid = threadIdx.x;
    const int m0 = blockIdx.y * BM;
    const int n0 = blockIdx.x * BN;

    const int w  = tid >> 5;
    const int wm = w >> 2;
    const int wn = w & 3;

    // Per-thread epilogue bias (columns fixed by tid)
    const int ec2 = tid & 63;
    const float2 bv = *(const float2*)(bias + n0 + ec2 * 2);

    wmma::fragment<wmma::accumulator, 16, 16, 16, float> acc[4][2];
#pragma unroll
    for (int i = 0; i < 4; i++)
#pragma unroll
        for (int j = 0; j < 2; j++)
            wmma::fill_fragment(acc[i][j], 0.f);

    const int arow = tid >> 3, ac8 = (tid & 7) * 8;
    const int brow = tid >> 4, bc8 = (tid & 15) * 8;

    const int T = K / BK;

    // Prologue: stage tiles 0 and 1
#pragma unroll
    for (int pt = 0; pt < 2; pt++) {
        const int kt = pt * BK;
        const __half* ag = &A[(size_t)(m0 + arow) * K + kt + ac8];
        const __half* bg = &Bm[(size_t)(kt + brow) * N + n0 + bc8];
        __half* asd = smh + pt * STG_HALVES;
        __half* bsd = asd + BM * ASTRH;
#pragma unroll
        for (int p = 0; p < 4; p++)
            cpa16(&asd[(arow + p * 32) * ASTRH + ac8], ag + (size_t)(p * 32) * K);
#pragma unroll
        for (int p = 0; p < 4; p++)
            cpa16(&bsd[(brow + p * 16) * BSTR + bc8], bg + (size_t)(p * 16) * N);
        cpa_commit();
    }

    for (int t = 0; t < T; t++) {
        if (t + 1 < T) cpa_wait<1>();
        else           cpa_wait<0>();
        __syncthreads();   // stage t visible to all; all warps done with t-1

        if (t + 2 < T) {
            const int st = (t + 2) % NSTG;   // == (t-1)%NSTG, drained above
            const int kt = (t + 2) * BK;
            const __half* ag = &A[(size_t)(m0 + arow) * K + kt + ac8];
            const __half* bg = &Bm[(size_t)(kt + brow) * N + n0 + bc8];
            __half* asd = smh + st * STG_HALVES;
            __half* bsd = asd + BM * ASTRH;
#pragma unroll
            for (int p = 0; p < 4; p++)
                cpa16(&asd[(arow + p * 32) * ASTRH + ac8], ag + (size_t)(p * 32) * K);
#pragma unroll
            for (int p = 0; p < 4; p++)
                cpa16(&bsd[(brow + p * 16) * BSTR + bc8], bg + (size_t)(p * 16) * N);
            cpa_commit();
        }

        const __half* asrc = smh + (t % NSTG) * STG_HALVES;
        const __half* bsrc = asrc + BM * ASTRH;

#pragma unroll
        for (int kk = 0; kk < BK; kk += 16) {
            wmma::fragment<wmma::matrix_a, 16, 16, 16, __half, wmma::row_major> af[4];
            wmma::fragment<wmma::matrix_b, 16, 16, 16, __half, wmma::row_major> bf[2];
#pragma unroll
            for (int i = 0; i < 4; i++)
                wmma::load_matrix_sync(af[i], &asrc[(wm * 64 + i * 16) * ASTRH + kk], ASTRH);
#pragma unroll
            for (int j = 0; j < 2; j++)
                wmma::load_matrix_sync(bf[j], &bsrc[kk * BSTR + wn * 32 + j * 16], BSTR);
#pragma unroll
            for (int i = 0; i < 4; i++)
#pragma unroll
                for (int j = 0; j < 2; j++)
                    wmma::mma_sync(acc[i][j], af[i], bf[j], acc[i][j]);
        }
    }
    __syncthreads();  // all compute done before smem reuse as epilogue tile

    // Staged epilogue: reuse stage smem as 128x132 fp32 tile (67.6 KB).
    float* ct = (float*)smraw;
#pragma unroll
    for (int i = 0; i < 4; i++)
#pragma unroll
        for (int j = 0; j < 2; j++)
            wmma::store_matrix_sync(
                ct + (wm * 64 + i * 16) * CTSTR + wn * 32 + j * 16,
                acc[i][j], CTSTR, wmma::mem_row_major);
    __syncthreads();

    if (HALF_OUT) {
        __half* Ch = (__half*)Cout;
#pragma unroll
        for (int p = 0; p < 32; p++) {
            const int idx = tid + p * 256;
            const int r = idx >> 6;
            __half2 v = __floats2half2_rn(ct[r * CTSTR + ec2 * 2] + bv.x,
                                          ct[r * CTSTR + ec2 * 2 + 1] + bv.y);
            *(__half2*)(Ch + (size_t)(m0 + r) * N + n0 + ec2 * 2) = v;
        }
    } else {
        float* Cf = (float*)Cout;
#pragma unroll
        for (int p = 0; p < 32; p++) {
            const int idx = tid + p * 256;
            const int r = idx >> 6;
            float2 v;
            v.x = ct[r * CTSTR + ec2 * 2] + bv.x;
            v.y = ct[r * CTSTR + ec2 * 2 + 1] + bv.y;
            *(float2*)(Cf + (size_t)(m0 + r) * N + n0 + ec2 * 2) = v;
        }
    }
}

__global__ __launch_bounds__(256, 2) void gemm_qkv_k(const float* __restrict__ bias)
{
    gemm_body<true>(g_x, g_wqkv, bias, g_qkv, MROWS, C3, CC);
}

__global__ __launch_bounds__(256, 2) void gemm_proj_k(
    const float* __restrict__ bias, float* __restrict__ C)
{
    gemm_body<false>(g_att, g_wproj, bias, C, MROWS, CC, CC);
}

// ---------------------------------------------------------------------------
// Tensorized fp16 attention: one CTA per (batch, head), 512 threads (16 warps).
// Compacted K layout (256 rows): keys 0..195, Rh 196..222, Rw 223..249,
// zero pad 250..255 -> QK is 16 N-tiles (was 18). Query blocks sized
// {64,64,64,16} (196 = 3*64 + 4) so the tail block does 1/4 the work.
// QK^T wmma -> log2-softmax (packed f16 EX2, norm folded into fp16 P) ->
// PV wmma -> fp16 out.
// ---------------------------------------------------------------------------
#define AKSTR 72      // halves per K/V/Q row (64 + 8 pad)
#define SSTRF 264     // fp32 S row stride (256 + 8)
#define PSTR 232      // halves per P row

#define ASM_K (256 * AKSTR)
#define ASM_V (224 * AKSTR)
#define ASM_Q (64 * AKSTR)
#define ASM_P (64 * PSTR)
#define ASM_S (64 * SSTRF)
#define ATTN_SMEM_BYTES ((ASM_K + ASM_V + ASM_Q + ASM_P) * 2 + ASM_S * 4)

__global__ __launch_bounds__(512) void attn_kernel(
    const float* __restrict__ rph, const float* __restrict__ rpw)
{
    extern __shared__ char smraw[];
    __half* kS = (__half*)smraw;
    __half* vS = kS + ASM_K;
    __half* qS = vS + ASM_V;
    __half* pS = qS + ASM_Q;
    float*  sS = (float*)(pS + ASM_P);

    const int tid = threadIdx.x;
    const int wid = tid >> 5;
    const int head = blockIdx.x;
    const int b = head / NHEAD;
    const int h = head % NHEAD;

    const __half* gbase = g_qkv + (size_t)b * HWSZ * C3 + h * HDIM;

    // Zero pad rows: kS 250..255; vS 196..223
    {
        const uint4 z = make_uint4(0, 0, 0, 0);
        for (int i = tid; i < 6 * 9; i += 512) ((uint4*)(kS + 250 * AKSTR))[i] = z;
        for (int i = tid; i < 28 * 9; i += 512) ((uint4*)(vS + 196 * AKSTR))[i] = z;
    }
    // Stage K, V via cp.async (fp16 source)
    for (int i = tid; i < HWSZ * 8; i += 512) {
        int j = i >> 3, seg = (i & 7) * 8;
        cpa16(kS + j * AKSTR + seg, gbase + (size_t)j * C3 + 768 + seg);
        cpa16(vS + j * AKSTR + seg, gbase + (size_t)j * C3 + 1536 + seg);
    }
    cpa_commit();
    // Rel tables (fp32 -> fp16): Rh rows 196..222, Rw rows 223..249
    for (int i = tid; i < 27 * HDIM; i += 512) {
        int r = i >> 6, d = i & 63;
        kS[(196 + r) * AKSTR + d] = __float2half(rph[i]);
        kS[(223 + r) * AKSTR + d] = __float2half(rpw[i]);
    }
    cpa_wait<0>();
    __syncthreads();

    for (int blk = 0; blk < 4; blk++) {
        const int r0 = blk * 64;
        const int mtiles = (blk < 3) ? 4 : 1;  // 196 = 3*64 + 4 -> last: 1 tile

        // --- Stage Q block (fp16), zero invalid rows ---
        for (int i = tid; i < mtiles * 16 * 8; i += 512) {
            int r = i >> 3, seg = (i & 7) * 8;
            uint4 v = make_uint4(0, 0, 0, 0);
            if (r0 + r < HWSZ)
                v = *(const uint4*)(gbase + (size_t)(r0 + r) * C3 + seg);
            *(uint4*)(qS + r * AKSTR + seg) = v;
        }
        __syncthreads();

        // --- QK^T (+rel cols): mtiles x 16 tiles of 16x16, k=64 ---
        for (int t = wid; t < mtiles * 16; t += 16) {
            const int mt = t >> 4, nt = t & 15;
            wmma::fragment<wmma::accumulator, 16, 16, 16, float> acc;
            wmma::fill_fragment(acc, 0.f);
#pragma unroll
            for (int ks = 0; ks < 4; ks++) {
                wmma::fragment<wmma::matrix_a, 16, 16, 16, __half, wmma::row_major> af;
                wmma::fragment<wmma::matrix_b, 16, 16, 16, __half, wmma::col_major> bf;
                wmma::load_matrix_sync(af, qS + mt * 16 * AKSTR + ks * 16, AKSTR);
                wmma::load_matrix_sync(bf, kS + nt * 16 * AKSTR + ks * 16, AKSTR);
                wmma::mma_sync(acc, af, bf, acc);
            }
            wmma::store_matrix_sync(sS + mt * 16 * SSTRF + nt * 16, acc, SSTRF,
                                    wmma::mem_row_major);
        }
        __syncthreads();

        // --- Softmax (8 threads/row, 28 cols each), P = e/sum in fp16 ---
        if ((tid >> 3) < mtiles * 16) {
            const int r = tid >> 3, sub = tid & 7;
            const int qr = r0 + r;
            const int qv = (qr < HWSZ) ? qr : 0;
            const int hq = qv / 14, wq = qv % 14;
            const float* srow = sS + r * SSTRF;
            float e[28];
            float lsum = 0.f;
#pragma unroll
            for (int i = 0; i < 28; i += 2) {
                float s01[2];
#pragma unroll
                for (int u = 0; u < 2; u++) {
                    int j = sub + (i + u) * 8;
                    if (j < HWSZ) {
                        int i1 = hq - j / 14 + 13;
                        int i2 = wq - j % 14 + 13;
                        s01[u] = (srow[j] * 0.125f + srow[196 + i1] + srow[223 + i2])
                                 * LOG2E;
                    } else {
                        s01[u] = -30.0f;  // exp2 -> 0 in f16
                    }
                }
                float2 ee = exp2_2(s01[0], s01[1]);
                e[i] = ee.x;
                e[i + 1] = ee.y;
                lsum += ee.x + ee.y;
            }
#pragma unroll
            for (int o = 4; o > 0; o >>= 1)
                lsum += __shfl_xor_sync(0xffffffffu, lsum, o);
            const float inv = 1.f / lsum;
            __half* prow = pS + r * PSTR;
#pragma unroll
            for (int i = 0; i < 28; i++)
                prow[sub + i * 8] = __float2half(e[i] * inv);
        }
        __syncthreads();

        // --- PV: mtiles x 4 tiles of 16x16, k=224 (14 steps); O -> sS ---
        if (wid < mtiles * 4) {
            const int mt = wid >> 2, nt = wid & 3;
            wmma::fragment<wmma::accumulator, 16, 16, 16, float> acc;
            wmma::fill_fragment(acc, 0.f);
#pragma unroll
            for (int ks = 0; ks < 14; ks++) {
                wmma::fragment<wmma::matrix_a, 16, 16, 16, __half, wmma::row_major> af;
                wmma::fragment<wmma::matrix_b, 16, 16, 16, __half, wmma::row_major> bf;
                wmma::load_matrix_sync(af, pS + mt * 16 * PSTR + ks * 16, PSTR);
                wmma::load_matrix_sync(bf, vS + ks * 16 * AKSTR + nt * 16, AKSTR);
                wmma::mma_sync(acc, af, bf, acc);
            }
            wmma::store_matrix_sync(sS + mt * 16 * SSTRF + nt * 16, acc, SSTRF,
                                    wmma::mem_row_major);
        }
        __syncthreads();

        // --- Store valid O rows (fp16) ---
        {
            const int lim = mtiles * 16;
            const int nv = (HWSZ - r0 < lim) ? (HWSZ - r0) : lim;
            __half* gout = g_att + ((size_t)b * HWSZ + r0) * CC + h * HDIM;
            for (int idx = tid; idx < lim * 32; idx += 512) {
                int r = idx >> 5, c2 = idx & 31;
                if (r < nv) {
                    __half2 v = __floats2half2_rn(sS[r * SSTRF + c2 * 2],
                                                  sS[r * SSTRF + c2 * 2 + 1]);
                    *(__half2*)(gout + (size_t)r * CC + c2 * 2) = v;
                }
            }
        }
        __syncthreads();
    }
}

// ---------------------------------------------------------------------------
extern "C" void kernel_launch(void* const* d_in, const int* in_sizes, int n_in,
                              void* d_out, int out_size)
{
    const float* x      = (const float*)d_in[0]; // (25088, 768)
    const float* w_qkv  = (const float*)d_in[1]; // (768, 2304)
    const float* b_qkv  = (const float*)d_in[2]; // (2304,)
    const float* rph    = (const float*)d_in[3]; // (27, 64)
    const float* rpw    = (const float*)d_in[4]; // (27, 64)
    const float* w_proj = (const float*)d_in[5]; // (768, 768)
    const float* b_proj = (const float*)d_in[6]; // (768,)
    float* out = (float*)d_out;                  // (25088, 768)

    __half *d_x, *d_wqkv, *d_wproj;
    cudaGetSymbolAddress((void**)&d_x, g_x);
    cudaGetSymbolAddress((void**)&d_wqkv, g_wqkv);
    cudaGetSymbolAddress((void**)&d_wproj, g_wproj);

    cudaFuncSetAttribute(gemm_qkv_k,
                         cudaFuncAttributeMaxDynamicSharedMemorySize,
                         GEMM_SMEM_BYTES);
    cudaFuncSetAttribute(gemm_proj_k,
                         cudaFuncAttributeMaxDynamicSharedMemorySize,
                         GEMM_SMEM_BYTES);
    cudaFuncSetAttribute(attn_kernel,
                         cudaFuncAttributeMaxDynamicSharedMemorySize,
                         ATTN_SMEM_BYTES);

    // Convert GEMM inputs to fp16
    {
        int n4 = MROWS * CC / 4;
        to_half_kernel<<<(n4 + 255) / 256, 256>>>(x, d_x, n4);
        n4 = CC * C3 / 4;
        to_half_kernel<<<(n4 + 255) / 256, 256>>>(w_qkv, d_wqkv, n4);
        n4 = CC * CC / 4;
        to_half_kernel<<<(n4 + 255) / 256, 256>>>(w_proj, d_wproj, n4);
    }

    dim3 g1(C3 / BN, MROWS / BM);   // 18 x 196
    gemm_qkv_k<<<g1, 256, GEMM_SMEM_BYTES>>>(b_qkv);

    attn_kernel<<<NHEADS_TOTAL, 512, ATTN_SMEM_BYTES>>>(rph, rpw);

    dim3 g2(CC / BN, MROWS / BM);   // 6 x 196
    gemm_proj_k<<<g2, 256, GEMM_SMEM_BYTES>>>(b_proj, out);
}